// round 9
// baseline (speedup 1.0000x reference)
#include <cuda_runtime.h>
#include <cuda_bf16.h>
#include <cstdint>

#define BATCH 4
#define CDIM 256
#define HH 128
#define WW 128
#define NPIX (HH*WW)
#define HEADS 8
#define DHEAD 32
#define HALO 3
#define WINS 14
#define NBLK 256
#define NQ 64
#define NKEY 196
#define MTOT (BATCH*NPIX)
#define SCALE 0.17677669529663687f

// ---- scratch: bf16 hi/lo pairs ----
__device__ __nv_bfloat16 g_xh [(size_t)MTOT * CDIM];
__device__ __nv_bfloat16 g_xl [(size_t)MTOT * CDIM];
__device__ __nv_bfloat16 g_qh [(size_t)MTOT * CDIM];
__device__ __nv_bfloat16 g_ql [(size_t)MTOT * CDIM];
__device__ __nv_bfloat16 g_kvh[(size_t)MTOT * 2 * CDIM];
__device__ __nv_bfloat16 g_kvl[(size_t)MTOT * 2 * CDIM];
__device__ __nv_bfloat16 g_ch [(size_t)MTOT * CDIM];
__device__ __nv_bfloat16 g_cl [(size_t)MTOT * CDIM];
__device__ __nv_bfloat16 g_wh [(size_t)1024 * CDIM];
__device__ __nv_bfloat16 g_wl [(size_t)1024 * CDIM];

// ---------------- helpers ----------------
__device__ __forceinline__ uint32_t smem_u32(const void* p) {
    uint32_t a;
    asm("{ .reg .u64 t; cvta.to.shared.u64 t, %1; cvt.u32.u64 %0, t; }" : "=r"(a) : "l"(p));
    return a;
}
__device__ __forceinline__ void ldm_x4(uint32_t& r0, uint32_t& r1, uint32_t& r2, uint32_t& r3,
                                       uint32_t addr) {
    asm volatile("ldmatrix.sync.aligned.m8n8.x4.shared.b16 {%0,%1,%2,%3}, [%4];"
                 : "=r"(r0), "=r"(r1), "=r"(r2), "=r"(r3) : "r"(addr));
}
__device__ __forceinline__ void ldm_x4t(uint32_t& r0, uint32_t& r1, uint32_t& r2, uint32_t& r3,
                                        uint32_t addr) {
    asm volatile("ldmatrix.sync.aligned.m8n8.x4.trans.shared.b16 {%0,%1,%2,%3}, [%4];"
                 : "=r"(r0), "=r"(r1), "=r"(r2), "=r"(r3) : "r"(addr));
}
__device__ __forceinline__ void ldm_x2(uint32_t& r0, uint32_t& r1, uint32_t addr) {
    asm volatile("ldmatrix.sync.aligned.m8n8.x2.shared.b16 {%0,%1}, [%2];"
                 : "=r"(r0), "=r"(r1) : "r"(addr));
}
__device__ __forceinline__ void mma_bf16(float* d,
                                         uint32_t a0, uint32_t a1, uint32_t a2, uint32_t a3,
                                         uint32_t b0, uint32_t b1) {
    asm volatile("mma.sync.aligned.m16n8k16.row.col.f32.bf16.bf16.f32 "
                 "{%0,%1,%2,%3}, {%4,%5,%6,%7}, {%8,%9}, {%0,%1,%2,%3};"
                 : "+f"(d[0]), "+f"(d[1]), "+f"(d[2]), "+f"(d[3])
                 : "r"(a0), "r"(a1), "r"(a2), "r"(a3), "r"(b0), "r"(b1));
}
__device__ __forceinline__ void split2(float x, float y, uint32_t& hi, uint32_t& lo) {
    __nv_bfloat162 h2, l2;
    h2.x = __float2bfloat16_rn(x);
    h2.y = __float2bfloat16_rn(y);
    l2.x = __float2bfloat16_rn(x - __bfloat162float(h2.x));
    l2.y = __float2bfloat16_rn(y - __bfloat162float(h2.y));
    hi = *(uint32_t*)&h2;
    lo = *(uint32_t*)&l2;
}
__device__ __forceinline__ void cp16(uint32_t saddr, const void* g) {
    asm volatile("cp.async.cg.shared.global [%0], [%1], 16;" :: "r"(saddr), "l"(g));
}
#define CP_COMMIT() asm volatile("cp.async.commit_group;" ::: "memory")
#define CP_WAIT1()  asm volatile("cp.async.wait_group 1;" ::: "memory")
#define CP_WAIT0()  asm volatile("cp.async.wait_group 0;" ::: "memory")

// ============================================================================
// x[b][c][p] -> x_t[(b,p)][c] split to bf16 hi/lo
// ============================================================================
__global__ __launch_bounds__(256) void transpose_x(const float* __restrict__ x) {
    __shared__ float t[32][33];
    const int b = blockIdx.z, c0 = blockIdx.y * 32, p0 = blockIdx.x * 32;
    const int tx = threadIdx.x, ty = threadIdx.y;
    const float* src = x + (size_t)b * CDIM * NPIX;
    #pragma unroll
    for (int i = ty; i < 32; i += 8)
        t[i][tx] = src[(size_t)(c0 + i) * NPIX + p0 + tx];
    __syncthreads();
    #pragma unroll
    for (int i = ty; i < 32; i += 8) {
        const float v = t[tx][i];
        const size_t o = ((size_t)b * NPIX + p0 + i) * CDIM + c0 + tx;
        const __nv_bfloat16 h = __float2bfloat16_rn(v);
        g_xh[o] = h;
        g_xl[o] = __float2bfloat16_rn(v - __bfloat162float(h));
    }
}

__global__ __launch_bounds__(256) void split_w(const float* __restrict__ wq,
                                               const float* __restrict__ wkv,
                                               const float* __restrict__ fcw) {
    const int idx = blockIdx.x * 256 + threadIdx.x;
    const int r = idx >> 8, c = idx & 255;
    float v;
    if (r < 256) v = wq[r * 256 + c];
    else if (r < 768) v = wkv[(r - 256) * 256 + c];
    else v = fcw[(r - 768) * 256 + c];
    const __nv_bfloat16 h = __float2bfloat16_rn(v);
    g_wh[idx] = h;
    g_wl[idx] = __float2bfloat16_rn(v - __bfloat162float(h));
}

// ============================================================================
// TN GEMM via mma.sync bf16 3-term, cp.async 2-stage pipeline. Tile 128x128.
// mode 0: write bf16 hi/lo to Ch/Cl. mode 1: fp32 +bias, scatter to BCHW out.
// ============================================================================
#define LROW 40
#define GEMM_SMEM (2 * 40960)

__global__ __launch_bounds__(256) void gemm_mma(const __nv_bfloat16* __restrict__ Ah,
                                                const __nv_bfloat16* __restrict__ Al,
                                                const __nv_bfloat16* __restrict__ Bh,
                                                const __nv_bfloat16* __restrict__ Bl,
                                                __nv_bfloat16* __restrict__ Ch,
                                                __nv_bfloat16* __restrict__ Cl,
                                                int ldc, int mode,
                                                const float* __restrict__ fcb,
                                                float* __restrict__ out) {
    extern __shared__ __align__(16) char gsm[];
    const uint32_t ub = smem_u32(gsm);

    const int tid = threadIdx.x, wid = tid >> 5, lane = tid & 31;
    const int wm = wid >> 2, wn = wid & 3;
    const size_t m0 = (size_t)blockIdx.x * 128;
    const size_t n0 = (size_t)blockIdx.y * 128;

    int c_mat[4], c_row[4], c_cell[4];
    #pragma unroll
    for (int r = 0; r < 4; r++) {
        const int id = tid + 256 * r;
        c_mat[r] = id >> 9;
        c_row[r] = (id >> 2) & 127;
        c_cell[r] = id & 3;
    }

    float acc[4][4][4];
    #pragma unroll
    for (int a = 0; a < 4; a++)
        #pragma unroll
        for (int b = 0; b < 4; b++)
            #pragma unroll
            for (int c = 0; c < 4; c++) acc[a][b][c] = 0.f;

    const int i8 = lane & 7, g = lane >> 3;
    const int a_r = wm * 64 + ((g & 1) << 3) + i8;
    const int a_c = (g >> 1) << 3;
    const int b_r = wn * 32 + i8;
    const int b_sel = (lane >> 3) & 1;

    auto issue = [&](int it, int st) {
        #pragma unroll
        for (int r = 0; r < 4; r++) {
            const size_t off = ((c_mat[r] ? n0 : m0) + c_row[r]) * CDIM + it * 32 + c_cell[r] * 8;
            const uint32_t dst = ub + st * 40960 + c_mat[r] * 20480
                               + (c_row[r] * LROW + c_cell[r] * 8) * 2;
            cp16(dst, (c_mat[r] ? Bh : Ah) + off);
            cp16(dst + 10240, (c_mat[r] ? Bl : Al) + off);
        }
    };

    issue(0, 0);
    CP_COMMIT();

    for (int it = 0; it < 8; it++) {
        if (it < 7) { issue(it + 1, (it + 1) & 1); CP_COMMIT(); CP_WAIT1(); }
        else CP_WAIT0();
        __syncthreads();

        const uint32_t uAh = ub + (it & 1) * 40960;
        const uint32_t uAl = uAh + 10240;
        const uint32_t uBh = uAh + 20480;
        const uint32_t uBl = uAh + 30720;

        #pragma unroll
        for (int ks = 0; ks < 2; ks++) {
            const int kb = ks * 16;
            uint32_t ah[4][4], al[4][4];
            #pragma unroll
            for (int ms = 0; ms < 4; ms++) {
                const uint32_t off = ((a_r + ms * 16) * LROW + kb + a_c) * 2;
                ldm_x4(ah[ms][0], ah[ms][1], ah[ms][2], ah[ms][3], uAh + off);
                ldm_x4(al[ms][0], al[ms][1], al[ms][2], al[ms][3], uAl + off);
            }
            #pragma unroll
            for (int ns = 0; ns < 4; ns++) {
                const uint32_t boff = ((b_r + ns * 8) * LROW + kb + b_sel * 8) * 2;
                uint32_t bh0, bh1, bl0, bl1;
                ldm_x2(bh0, bh1, uBh + boff);
                ldm_x2(bl0, bl1, uBl + boff);
                #pragma unroll
                for (int ms = 0; ms < 4; ms++) {
                    mma_bf16(acc[ms][ns], ah[ms][0], ah[ms][1], ah[ms][2], ah[ms][3], bh0, bh1);
                    mma_bf16(acc[ms][ns], ah[ms][0], ah[ms][1], ah[ms][2], ah[ms][3], bl0, bl1);
                    mma_bf16(acc[ms][ns], al[ms][0], al[ms][1], al[ms][2], al[ms][3], bh0, bh1);
                }
            }
        }
        __syncthreads();
    }

    const int er = lane >> 2, ec = (lane & 3) * 2;
    #pragma unroll
    for (int ms = 0; ms < 4; ms++) {
        #pragma unroll
        for (int ns = 0; ns < 4; ns++) {
            const float* d = acc[ms][ns];
            const size_t m = m0 + wm * 64 + ms * 16 + er;
            const int nl = (int)n0 + wn * 32 + ns * 8 + ec;
            if (mode == 0) {
                #pragma unroll
                for (int rr = 0; rr < 2; rr++) {
                    uint32_t hi, lo;
                    split2(d[rr * 2], d[rr * 2 + 1], hi, lo);
                    *(uint32_t*)&Ch[(m + rr * 8) * ldc + nl] = hi;
                    *(uint32_t*)&Cl[(m + rr * 8) * ldc + nl] = lo;
                }
            } else {
                #pragma unroll
                for (int rr = 0; rr < 2; rr++) {
                    const size_t mm = m + rr * 8;
                    const int b = (int)(mm >> 14), n = (int)((mm >> 6) & 255), q = (int)(mm & 63);
                    const int orow = ((n >> 4) << 3) + (q >> 3);
                    const int ocol = ((n & 15) << 3) + (q & 7);
                    const size_t base = (((size_t)b * CDIM) << 14) + (orow << 7) + ocol;
                    out[base + ((size_t)nl << 14)]       = d[rr * 2]     + fcb[nl];
                    out[base + ((size_t)(nl + 1) << 14)] = d[rr * 2 + 1] + fcb[nl + 1];
                }
            }
        }
    }
}

// ============================================================================
// MMA halo attention (R6 proven version). One CTA per (b, block, head).
// pair p = w>>1 handles queries 16p..16p+15; half hf = w&1 keys 112hf..+111.
// ============================================================================
#define ATT_SMEM 105216

__global__ __launch_bounds__(256, 2) void halo_attn(const float* __restrict__ rel_h,
                                                    const float* __restrict__ rel_w) {
    extern __shared__ __align__(16) char smx[];
    __nv_bfloat16* sQh = (__nv_bfloat16*)(smx);            // [64][40]
    __nv_bfloat16* sQl = (__nv_bfloat16*)(smx + 5120);
    __nv_bfloat16* sKh = (__nv_bfloat16*)(smx + 10240);    // [224][40]
    __nv_bfloat16* sKl = (__nv_bfloat16*)(smx + 28160);
    __nv_bfloat16* sVh = (__nv_bfloat16*)(smx + 46080);    // [224][40] key-major
    __nv_bfloat16* sVl = (__nv_bfloat16*)(smx + 64000);
    float* bwv  = (float*)(smx + 81920);                   // [64][14]
    float* bhv  = (float*)(smx + 85504);
    float* rhs  = (float*)(smx + 89088);                   // [27][32]
    float* rws  = (float*)(smx + 92544);
    float* redm = (float*)(smx + 96000);                   // [4][2][16]
    float* reds = (float*)(smx + 96512);
    float* ctxb = (float*)(smx + 97024);                   // [64][32]

    const int bid = blockIdx.x;
    const int h = bid & 7;
    const int n = (bid >> 3) & 255;
    const int b = bid >> 11;
    const int r0 = (n >> 4) << 3;
    const int c0 = (n & 15) << 3;
    const int tid = threadIdx.x;

    // ---- load Q ----
    {
        const int row = tid >> 2, cell = tid & 3;
        const int pix = (r0 + (row >> 3)) * WW + c0 + (row & 7);
        const size_t gr = ((size_t)b * NPIX + pix) * CDIM + h * DHEAD + cell * 8;
        *(uint4*)(sQh + row * 40 + cell * 8) = *(const uint4*)(g_qh + gr);
        *(uint4*)(sQl + row * 40 + cell * 8) = *(const uint4*)(g_ql + gr);
    }
    // ---- load K/V windows, zero pads ----
    for (int t = tid; t < 1792; t += 256) {
        const int kj = t >> 3, rem = t & 7;
        const int mat = rem >> 2, cell = rem & 3;
        const int rr = r0 - HALO + kj / WINS;
        const int cc = c0 - HALO + kj % WINS;
        uint4 vh = make_uint4(0, 0, 0, 0), vl = vh;
        if (kj < NKEY && rr >= 0 && rr < HH && cc >= 0 && cc < WW) {
            const size_t off = ((size_t)b * NPIX + rr * WW + cc) * (2 * CDIM)
                             + (mat ? CDIM : 0) + h * DHEAD + cell * 8;
            vh = *(const uint4*)(g_kvh + off);
            vl = *(const uint4*)(g_kvl + off);
        }
        __nv_bfloat16* dh = (mat ? sVh : sKh) + kj * 40 + cell * 8;
        __nv_bfloat16* dl = (mat ? sVl : sKl) + kj * 40 + cell * 8;
        *(uint4*)dh = vh;
        *(uint4*)dl = vl;
    }
    for (int t = tid; t < 27 * 32; t += 256) {
        rhs[t] = rel_h[t];
        rws[t] = rel_w[t];
    }
    __syncthreads();

    // ---- per-query bias tables ----
    for (int t = tid; t < 64 * WINS; t += 256) {
        const int q = t / WINS, j = t % WINS;
        const int y = q & 7, x = q >> 3;
        const float* rw = &rws[(j - y + WINS - 1) * 32];
        const float* rh = &rhs[(j - x + WINS - 1) * 32];
        float sw = 0.f, sh = 0.f;
        #pragma unroll
        for (int d = 0; d < 32; d++) {
            const float qv = __bfloat162float(sQh[q * 40 + d]) + __bfloat162float(sQl[q * 40 + d]);
            sw += qv * rw[d];
            sh += qv * rh[d];
        }
        bwv[t] = sw;
        bhv[t] = sh;
    }
    __syncthreads();

    const int w = tid >> 5, lane = tid & 31;
    const int p = w >> 1, hf = w & 1;
    const int q0 = p * 16, kb0 = hf * 112;
    const int gid = lane >> 2, tg = lane & 3;
    const int i8 = lane & 7;

    const uint32_t uQh = smem_u32(sQh), uQl = smem_u32(sQl);
    const uint32_t uKh = smem_u32(sKh), uKl = smem_u32(sKl);
    const uint32_t uVh = smem_u32(sVh), uVl = smem_u32(sVl);

    // ---- score MMAs: sc[14 n-blocks][4] ----
    float sc[14][4];
    #pragma unroll
    for (int nb = 0; nb < 14; nb++)
        #pragma unroll
        for (int c = 0; c < 4; c++) sc[nb][c] = 0.f;

    const int a_row = q0 + (((lane >> 3) & 1) << 3) + i8;
    const int a_col = (lane >> 4) << 3;
    const int k_rowoff = ((lane >> 4) << 3) + i8;
    const int k_col = ((lane >> 3) & 1) << 3;

    #pragma unroll
    for (int ks = 0; ks < 2; ks++) {
        uint32_t ah[4], al[4];
        const uint32_t aoff = (a_row * 40 + ks * 16 + a_col) * 2;
        ldm_x4(ah[0], ah[1], ah[2], ah[3], uQh + aoff);
        ldm_x4(al[0], al[1], al[2], al[3], uQl + aoff);
        #pragma unroll
        for (int kb2 = 0; kb2 < 7; kb2++) {
            const uint32_t koff = ((kb0 + kb2 * 16 + k_rowoff) * 40 + ks * 16 + k_col) * 2;
            uint32_t bh0, bh1, bh2, bh3, bl0, bl1, bl2, bl3;
            ldm_x4(bh0, bh1, bh2, bh3, uKh + koff);
            ldm_x4(bl0, bl1, bl2, bl3, uKl + koff);
            mma_bf16(sc[2 * kb2], ah[0], ah[1], ah[2], ah[3], bh0, bh1);
            mma_bf16(sc[2 * kb2], ah[0], ah[1], ah[2], ah[3], bl0, bl1);
            mma_bf16(sc[2 * kb2], al[0], al[1], al[2], al[3], bh0, bh1);
            mma_bf16(sc[2 * kb2 + 1], ah[0], ah[1], ah[2], ah[3], bh2, bh3);
            mma_bf16(sc[2 * kb2 + 1], ah[0], ah[1], ah[2], ah[3], bl2, bl3);
            mma_bf16(sc[2 * kb2 + 1], al[0], al[1], al[2], al[3], bh2, bh3);
        }
    }

    // ---- scale + bias + mask, row max ----
    const int q_lo = q0 + gid, q_hi = q_lo + 8;
    float m0 = -1e30f, m1 = -1e30f;
    #pragma unroll
    for (int nb = 0; nb < 14; nb++) {
        #pragma unroll
        for (int c = 0; c < 2; c++) {
            const int k = kb0 + nb * 8 + tg * 2 + c;
            if (k < NKEY) {
                const int kd = (k * 74899) >> 20;
                const int km = k - kd * 14;
                sc[nb][c]     = sc[nb][c]     * SCALE + bwv[q_lo * 14 + km] + bhv[q_lo * 14 + kd];
                sc[nb][2 + c] = sc[nb][2 + c] * SCALE + bwv[q_hi * 14 + km] + bhv[q_hi * 14 + kd];
            } else {
                sc[nb][c] = -1e30f;
                sc[nb][2 + c] = -1e30f;
            }
            m0 = fmaxf(m0, sc[nb][c]);
            m1 = fmaxf(m1, sc[nb][2 + c]);
        }
    }
    m0 = fmaxf(m0, __shfl_xor_sync(0xffffffffu, m0, 1));
    m0 = fmaxf(m0, __shfl_xor_sync(0xffffffffu, m0, 2));
    m1 = fmaxf(m1, __shfl_xor_sync(0xffffffffu, m1, 1));
    m1 = fmaxf(m1, __shfl_xor_sync(0xffffffffu, m1, 2));
    if (tg == 0) {
        redm[(p * 2 + hf) * 16 + gid] = m0;
        redm[(p * 2 + hf) * 16 + gid + 8] = m1;
    }
    __syncthreads();
    m0 = fmaxf(redm[(p * 2) * 16 + gid], redm[(p * 2 + 1) * 16 + gid]);
    m1 = fmaxf(redm[(p * 2) * 16 + gid + 8], redm[(p * 2 + 1) * 16 + gid + 8]);

    float s0 = 0.f, s1 = 0.f;
    #pragma unroll
    for (int nb = 0; nb < 14; nb++) {
        #pragma unroll
        for (int c = 0; c < 2; c++) {
            sc[nb][c] = __expf(sc[nb][c] - m0);
            s0 += sc[nb][c];
            sc[nb][2 + c] = __expf(sc[nb][2 + c] - m1);
            s1 += sc[nb][2 + c];
        }
    }
    s0 += __shfl_xor_sync(0xffffffffu, s0, 1);
    s0 += __shfl_xor_sync(0xffffffffu, s0, 2);
    s1 += __shfl_xor_sync(0xffffffffu, s1, 1);
    s1 += __shfl_xor_sync(0xffffffffu, s1, 2);
    if (tg == 0) {
        reds[(p * 2 + hf) * 16 + gid] = s0;
        reds[(p * 2 + hf) * 16 + gid + 8] = s1;
    }
    __syncthreads();
    const float inv0 = 1.f / (reds[(p * 2) * 16 + gid] + reds[(p * 2 + 1) * 16 + gid]);
    const float inv1 = 1.f / (reds[(p * 2) * 16 + gid + 8] + reds[(p * 2 + 1) * 16 + gid + 8]);

    // ---- ctx = P @ V via trans-ldmatrix V, 3-term ----
    float acc[4][4];
    #pragma unroll
    for (int nd = 0; nd < 4; nd++)
        #pragma unroll
        for (int c = 0; c < 4; c++) acc[nd][c] = 0.f;

    const int v_rowoff = (((lane >> 3) & 1) << 3) + i8;
    const int v_col = (lane >> 4) << 3;

    #pragma unroll
    for (int kb = 0; kb < 7; kb++) {
        uint32_t pah[4], pal[4];
        split2(sc[2 * kb][0], sc[2 * kb][1], pah[0], pal[0]);
        split2(sc[2 * kb][2], sc[2 * kb][3], pah[1], pal[1]);
        split2(sc[2 * kb + 1][0], sc[2 * kb + 1][1], pah[2], pal[2]);
        split2(sc[2 * kb + 1][2], sc[2 * kb + 1][3], pah[3], pal[3]);

        const int vrow = kb0 + kb * 16 + v_rowoff;
        uint32_t vh[8], vl[8];
        ldm_x4t(vh[0], vh[1], vh[2], vh[3], uVh + (vrow * 40 + v_col) * 2);
        ldm_x4t(vh[4], vh[5], vh[6], vh[7], uVh + (vrow * 40 + 16 + v_col) * 2);
        ldm_x4t(vl[0], vl[1], vl[2], vl[3], uVl + (vrow * 40 + v_col) * 2);
        ldm_x4t(vl[4], vl[5], vl[6], vl[7], uVl + (vrow * 40 + 16 + v_col) * 2);

        #pragma unroll
        for (int nd = 0; nd < 4; nd++) {
            const uint32_t b0h = vh[(nd >> 1) * 4 + (nd & 1) * 2];
            const uint32_t b1h = vh[(nd >> 1) * 4 + (nd & 1) * 2 + 1];
            const uint32_t b0l = vl[(nd >> 1) * 4 + (nd & 1) * 2];
            const uint32_t b1l = vl[(nd >> 1) * 4 + (nd & 1) * 2 + 1];
            mma_bf16(acc[nd], pah[0], pah[1], pah[2], pah[3], b0h, b1h);
            mma_bf16(acc[nd], pah[0], pah[1], pah[2], pah[3], b0l, b1l);
            mma_bf16(acc[nd], pal[0], pal[1], pal[2], pal[3], b0h, b1h);
        }
    }

    // ---- combine halves, normalize, store bf16 hi/lo ctx ----
    if (hf == 0) {
        #pragma unroll
        for (int nd = 0; nd < 4; nd++) {
            *(float2*)&ctxb[(q0 + gid) * 32 + nd * 8 + tg * 2] = make_float2(acc[nd][0], acc[nd][1]);
            *(float2*)&ctxb[(q0 + gid + 8) * 32 + nd * 8 + tg * 2] = make_float2(acc[nd][2], acc[nd][3]);
        }
    }
    __syncthreads();
    if (hf == 1) {
        const size_t base = ((size_t)(b * NBLK + n) * NQ + q0 + gid) * CDIM + h * DHEAD;
        const size_t base8 = base + 8 * CDIM;
        #pragma unroll
        for (int nd = 0; nd < 4; nd++) {
            const int dcol = nd * 8 + tg * 2;
            const float2 o0 = *(const float2*)&ctxb[(q0 + gid) * 32 + dcol];
            const float2 o1 = *(const float2*)&ctxb[(q0 + gid + 8) * 32 + dcol];
            uint32_t hi, lo;
            split2((acc[nd][0] + o0.x) * inv0, (acc[nd][1] + o0.y) * inv0, hi, lo);
            *(uint32_t*)&g_ch[base + dcol] = hi;
            *(uint32_t*)&g_cl[base + dcol] = lo;
            split2((acc[nd][2] + o1.x) * inv1, (acc[nd][3] + o1.y) * inv1, hi, lo);
            *(uint32_t*)&g_ch[base8 + dcol] = hi;
            *(uint32_t*)&g_cl[base8 + dcol] = lo;
        }
    }
}

// ============================================================================
extern "C" void kernel_launch(void* const* d_in, const int* in_sizes, int n_in,
                              void* d_out, int out_size) {
    const float* x     = (const float*)d_in[0];
    const float* w_q   = (const float*)d_in[1];
    const float* w_kv  = (const float*)d_in[2];
    const float* fc_w  = (const float*)d_in[3];
    const float* fc_b  = (const float*)d_in[4];
    const float* rel_h = (const float*)d_in[5];
    const float* rel_w = (const float*)d_in[6];
    float* out = (float*)d_out;

    __nv_bfloat16 *xh, *xl, *qh, *ql, *kvh, *kvl, *ch, *cl, *wh, *wl;
    cudaGetSymbolAddress((void**)&xh, g_xh);
    cudaGetSymbolAddress((void**)&xl, g_xl);
    cudaGetSymbolAddress((void**)&qh, g_qh);
    cudaGetSymbolAddress((void**)&ql, g_ql);
    cudaGetSymbolAddress((void**)&kvh, g_kvh);
    cudaGetSymbolAddress((void**)&kvl, g_kvl);
    cudaGetSymbolAddress((void**)&ch, g_ch);
    cudaGetSymbolAddress((void**)&cl, g_cl);
    cudaGetSymbolAddress((void**)&wh, g_wh);
    cudaGetSymbolAddress((void**)&wl, g_wl);

    cudaFuncSetAttribute(gemm_mma, cudaFuncAttributeMaxDynamicSharedMemorySize, GEMM_SMEM);
    cudaFuncSetAttribute(halo_attn, cudaFuncAttributeMaxDynamicSharedMemorySize, ATT_SMEM);

    split_w<<<1024, 256>>>(w_q, w_kv, fc_w);
    transpose_x<<<dim3(NPIX / 32, CDIM / 32, BATCH), dim3(32, 8)>>>(x);
    gemm_mma<<<dim3(MTOT / 128, 2), 256, GEMM_SMEM>>>(xh, xl, wh, wl, qh, ql, CDIM, 0, nullptr, nullptr);
    gemm_mma<<<dim3(MTOT / 128, 4), 256, GEMM_SMEM>>>(xh, xl, wh + 256 * CDIM, wl + 256 * CDIM,
                                                      kvh, kvl, 2 * CDIM, 0, nullptr, nullptr);
    halo_attn<<<BATCH * NBLK * HEADS, 256, ATT_SMEM>>>(rel_h, rel_w);
    gemm_mma<<<dim3(MTOT / 128, 2), 256, GEMM_SMEM>>>(ch, cl, wh + 768 * CDIM, wl + 768 * CDIM,
                                                      nullptr, nullptr, 0, 1, fc_b, out);
}

// round 10
// speedup vs baseline: 1.5574x; 1.5574x over previous
#include <cuda_runtime.h>
#include <cuda_bf16.h>
#include <cstdint>

#define BATCH 4
#define CDIM 256
#define HH 128
#define WW 128
#define NPIX (HH*WW)
#define HEADS 8
#define DHEAD 32
#define HALO 3
#define WINS 14
#define NBLK 256
#define NQ 64
#define NKEY 196
#define MTOT (BATCH*NPIX)
#define SCALE 0.17677669529663687f

// ---- scratch: bf16 hi/lo pairs ----
__device__ __nv_bfloat16 g_xh [(size_t)MTOT * CDIM];
__device__ __nv_bfloat16 g_xl [(size_t)MTOT * CDIM];
__device__ __nv_bfloat16 g_qh [(size_t)MTOT * CDIM];
__device__ __nv_bfloat16 g_ql [(size_t)MTOT * CDIM];
__device__ __nv_bfloat16 g_kvh[(size_t)MTOT * 2 * CDIM];
__device__ __nv_bfloat16 g_kvl[(size_t)MTOT * 2 * CDIM];
__device__ __nv_bfloat16 g_ch [(size_t)MTOT * CDIM];
__device__ __nv_bfloat16 g_cl [(size_t)MTOT * CDIM];
__device__ __nv_bfloat16 g_wh [(size_t)1024 * CDIM];
__device__ __nv_bfloat16 g_wl [(size_t)1024 * CDIM];

// ---------------- helpers ----------------
__device__ __forceinline__ uint32_t smem_u32(const void* p) {
    uint32_t a;
    asm("{ .reg .u64 t; cvta.to.shared.u64 t, %1; cvt.u32.u64 %0, t; }" : "=r"(a) : "l"(p));
    return a;
}
__device__ __forceinline__ void ldm_x4(uint32_t& r0, uint32_t& r1, uint32_t& r2, uint32_t& r3,
                                       uint32_t addr) {
    asm volatile("ldmatrix.sync.aligned.m8n8.x4.shared.b16 {%0,%1,%2,%3}, [%4];"
                 : "=r"(r0), "=r"(r1), "=r"(r2), "=r"(r3) : "r"(addr));
}
__device__ __forceinline__ void ldm_x4t(uint32_t& r0, uint32_t& r1, uint32_t& r2, uint32_t& r3,
                                        uint32_t addr) {
    asm volatile("ldmatrix.sync.aligned.m8n8.x4.trans.shared.b16 {%0,%1,%2,%3}, [%4];"
                 : "=r"(r0), "=r"(r1), "=r"(r2), "=r"(r3) : "r"(addr));
}
__device__ __forceinline__ void ldm_x2(uint32_t& r0, uint32_t& r1, uint32_t addr) {
    asm volatile("ldmatrix.sync.aligned.m8n8.x2.shared.b16 {%0,%1}, [%2];"
                 : "=r"(r0), "=r"(r1) : "r"(addr));
}
__device__ __forceinline__ void mma_bf16(float* d,
                                         uint32_t a0, uint32_t a1, uint32_t a2, uint32_t a3,
                                         uint32_t b0, uint32_t b1) {
    asm volatile("mma.sync.aligned.m16n8k16.row.col.f32.bf16.bf16.f32 "
                 "{%0,%1,%2,%3}, {%4,%5,%6,%7}, {%8,%9}, {%0,%1,%2,%3};"
                 : "+f"(d[0]), "+f"(d[1]), "+f"(d[2]), "+f"(d[3])
                 : "r"(a0), "r"(a1), "r"(a2), "r"(a3), "r"(b0), "r"(b1));
}
__device__ __forceinline__ void split2(float x, float y, uint32_t& hi, uint32_t& lo) {
    __nv_bfloat162 h2, l2;
    h2.x = __float2bfloat16_rn(x);
    h2.y = __float2bfloat16_rn(y);
    l2.x = __float2bfloat16_rn(x - __bfloat162float(h2.x));
    l2.y = __float2bfloat16_rn(y - __bfloat162float(h2.y));
    hi = *(uint32_t*)&h2;
    lo = *(uint32_t*)&l2;
}

// ============================================================================
// x[b][c][p] -> x_t[(b,p)][c] split to bf16 hi/lo
// ============================================================================
__global__ __launch_bounds__(256) void transpose_x(const float* __restrict__ x) {
    __shared__ float t[32][33];
    const int b = blockIdx.z, c0 = blockIdx.y * 32, p0 = blockIdx.x * 32;
    const int tx = threadIdx.x, ty = threadIdx.y;
    const float* src = x + (size_t)b * CDIM * NPIX;
    #pragma unroll
    for (int i = ty; i < 32; i += 8)
        t[i][tx] = src[(size_t)(c0 + i) * NPIX + p0 + tx];
    __syncthreads();
    #pragma unroll
    for (int i = ty; i < 32; i += 8) {
        const float v = t[tx][i];
        const size_t o = ((size_t)b * NPIX + p0 + i) * CDIM + c0 + tx;
        const __nv_bfloat16 h = __float2bfloat16_rn(v);
        g_xh[o] = h;
        g_xl[o] = __float2bfloat16_rn(v - __bfloat162float(h));
    }
}

__global__ __launch_bounds__(256) void split_w(const float* __restrict__ wq,
                                               const float* __restrict__ wkv,
                                               const float* __restrict__ fcw) {
    const int idx = blockIdx.x * 256 + threadIdx.x;
    const int r = idx >> 8, c = idx & 255;
    float v;
    if (r < 256) v = wq[r * 256 + c];
    else if (r < 768) v = wkv[(r - 256) * 256 + c];
    else v = fcw[(r - 768) * 256 + c];
    const __nv_bfloat16 h = __float2bfloat16_rn(v);
    g_wh[idx] = h;
    g_wl[idx] = __float2bfloat16_rn(v - __bfloat162float(h));
}

// ============================================================================
// TN GEMM via mma.sync bf16 3-term (R6 proven: static smem, 2 CTAs/SM).
// mode 0: write bf16 hi/lo to Ch/Cl. mode 1: fp32 +bias, scatter to BCHW out.
// ============================================================================
#define LROW 40

__global__ __launch_bounds__(256) void gemm_mma(const __nv_bfloat16* __restrict__ Ah,
                                                const __nv_bfloat16* __restrict__ Al,
                                                const __nv_bfloat16* __restrict__ Bh,
                                                const __nv_bfloat16* __restrict__ Bl,
                                                __nv_bfloat16* __restrict__ Ch,
                                                __nv_bfloat16* __restrict__ Cl,
                                                int ldc, int mode,
                                                const float* __restrict__ fcb,
                                                float* __restrict__ out) {
    __shared__ __align__(16) __nv_bfloat16 sAh[128 * LROW];
    __shared__ __align__(16) __nv_bfloat16 sAl[128 * LROW];
    __shared__ __align__(16) __nv_bfloat16 sBh[128 * LROW];
    __shared__ __align__(16) __nv_bfloat16 sBl[128 * LROW];

    const int tid = threadIdx.x, wid = tid >> 5, lane = tid & 31;
    const int wm = wid >> 2, wn = wid & 3;
    const size_t m0 = (size_t)blockIdx.x * 128;
    const size_t n0 = (size_t)blockIdx.y * 128;

    const uint32_t uAh = smem_u32(sAh), uAl = smem_u32(sAl);
    const uint32_t uBh = smem_u32(sBh), uBl = smem_u32(sBl);

    float acc[4][4][4];
    #pragma unroll
    for (int a = 0; a < 4; a++)
        #pragma unroll
        for (int b = 0; b < 4; b++)
            #pragma unroll
            for (int c = 0; c < 4; c++) acc[a][b][c] = 0.f;

    const int i8 = lane & 7, g = lane >> 3;
    const int a_r = wm * 64 + ((g & 1) << 3) + i8;
    const int a_c = (g >> 1) << 3;
    const int b_r = wn * 32 + i8;
    const int b_sel = (lane >> 3) & 1;

    for (int it = 0; it < 8; it++) {
        if (it) __syncthreads();
        #pragma unroll
        for (int r = 0; r < 4; r++) {
            const int id = tid + 256 * r;
            const int mat = id >> 9;
            const int row = (id >> 2) & 127;
            const int cell = id & 3;
            const size_t off = ((mat ? n0 : m0) + row) * CDIM + it * 32 + cell * 8;
            const uint4 vh = *(const uint4*)((mat ? Bh : Ah) + off);
            const uint4 vl = *(const uint4*)((mat ? Bl : Al) + off);
            __nv_bfloat16* dh = (mat ? sBh : sAh) + row * LROW + cell * 8;
            __nv_bfloat16* dl = (mat ? sBl : sAl) + row * LROW + cell * 8;
            *(uint4*)dh = vh;
            *(uint4*)dl = vl;
        }
        __syncthreads();

        #pragma unroll
        for (int ks = 0; ks < 2; ks++) {
            const int kb = ks * 16;
            uint32_t ah[4][4], al[4][4];
            #pragma unroll
            for (int ms = 0; ms < 4; ms++) {
                const uint32_t off = ((a_r + ms * 16) * LROW + kb + a_c) * 2;
                ldm_x4(ah[ms][0], ah[ms][1], ah[ms][2], ah[ms][3], uAh + off);
                ldm_x4(al[ms][0], al[ms][1], al[ms][2], al[ms][3], uAl + off);
            }
            #pragma unroll
            for (int ns = 0; ns < 4; ns++) {
                const uint32_t boff = ((b_r + ns * 8) * LROW + kb + b_sel * 8) * 2;
                uint32_t bh0, bh1, bl0, bl1;
                ldm_x2(bh0, bh1, uBh + boff);
                ldm_x2(bl0, bl1, uBl + boff);
                #pragma unroll
                for (int ms = 0; ms < 4; ms++) {
                    mma_bf16(acc[ms][ns], ah[ms][0], ah[ms][1], ah[ms][2], ah[ms][3], bh0, bh1);
                    mma_bf16(acc[ms][ns], ah[ms][0], ah[ms][1], ah[ms][2], ah[ms][3], bl0, bl1);
                    mma_bf16(acc[ms][ns], al[ms][0], al[ms][1], al[ms][2], al[ms][3], bh0, bh1);
                }
            }
        }
    }

    const int er = lane >> 2, ec = (lane & 3) * 2;
    #pragma unroll
    for (int ms = 0; ms < 4; ms++) {
        #pragma unroll
        for (int ns = 0; ns < 4; ns++) {
            const float* d = acc[ms][ns];
            const size_t m = m0 + wm * 64 + ms * 16 + er;
            const int nl = (int)n0 + wn * 32 + ns * 8 + ec;
            if (mode == 0) {
                #pragma unroll
                for (int rr = 0; rr < 2; rr++) {
                    uint32_t hi, lo;
                    split2(d[rr * 2], d[rr * 2 + 1], hi, lo);
                    *(uint32_t*)&Ch[(m + rr * 8) * ldc + nl] = hi;
                    *(uint32_t*)&Cl[(m + rr * 8) * ldc + nl] = lo;
                }
            } else {
                #pragma unroll
                for (int rr = 0; rr < 2; rr++) {
                    const size_t mm = m + rr * 8;
                    const int b = (int)(mm >> 14), n = (int)((mm >> 6) & 255), q = (int)(mm & 63);
                    const int orow = ((n >> 4) << 3) + (q >> 3);
                    const int ocol = ((n & 15) << 3) + (q & 7);
                    const size_t base = (((size_t)b * CDIM) << 14) + (orow << 7) + ocol;
                    out[base + ((size_t)nl << 14)]       = d[rr * 2]     + fcb[nl];
                    out[base + ((size_t)(nl + 1) << 14)] = d[rr * 2 + 1] + fcb[nl + 1];
                }
            }
        }
    }
}

// ============================================================================
// MMA halo attention (R6 structure; rel tables padded to stride 33 to kill
// the 32-way bank conflicts in the bias-table build).
// ============================================================================
#define RSTRIDE 33
#define ATT_SMEM 105440

__global__ __launch_bounds__(256, 2) void halo_attn(const float* __restrict__ rel_h,
                                                    const float* __restrict__ rel_w) {
    extern __shared__ __align__(16) char smx[];
    __nv_bfloat16* sQh = (__nv_bfloat16*)(smx);            // [64][40]
    __nv_bfloat16* sQl = (__nv_bfloat16*)(smx + 5120);
    __nv_bfloat16* sKh = (__nv_bfloat16*)(smx + 10240);    // [224][40]
    __nv_bfloat16* sKl = (__nv_bfloat16*)(smx + 28160);
    __nv_bfloat16* sVh = (__nv_bfloat16*)(smx + 46080);    // [224][40] key-major
    __nv_bfloat16* sVl = (__nv_bfloat16*)(smx + 64000);
    float* bwv  = (float*)(smx + 81920);                   // [64][14]
    float* bhv  = (float*)(smx + 85504);
    float* rhs  = (float*)(smx + 89088);                   // [27][33]
    float* rws  = (float*)(smx + 92656);                   // [27][33]
    float* redm = (float*)(smx + 96224);                   // [4][2][16]
    float* reds = (float*)(smx + 96736);
    float* ctxb = (float*)(smx + 97248);                   // [64][32]

    const int bid = blockIdx.x;
    const int h = bid & 7;
    const int n = (bid >> 3) & 255;
    const int b = bid >> 11;
    const int r0 = (n >> 4) << 3;
    const int c0 = (n & 15) << 3;
    const int tid = threadIdx.x;

    // ---- load Q ----
    {
        const int row = tid >> 2, cell = tid & 3;
        const int pix = (r0 + (row >> 3)) * WW + c0 + (row & 7);
        const size_t gr = ((size_t)b * NPIX + pix) * CDIM + h * DHEAD + cell * 8;
        *(uint4*)(sQh + row * 40 + cell * 8) = *(const uint4*)(g_qh + gr);
        *(uint4*)(sQl + row * 40 + cell * 8) = *(const uint4*)(g_ql + gr);
    }
    // ---- load K/V windows, zero pads ----
    for (int t = tid; t < 1792; t += 256) {
        const int kj = t >> 3, rem = t & 7;
        const int mat = rem >> 2, cell = rem & 3;
        const int rr = r0 - HALO + kj / WINS;
        const int cc = c0 - HALO + kj % WINS;
        uint4 vh = make_uint4(0, 0, 0, 0), vl = vh;
        if (kj < NKEY && rr >= 0 && rr < HH && cc >= 0 && cc < WW) {
            const size_t off = ((size_t)b * NPIX + rr * WW + cc) * (2 * CDIM)
                             + (mat ? CDIM : 0) + h * DHEAD + cell * 8;
            vh = *(const uint4*)(g_kvh + off);
            vl = *(const uint4*)(g_kvl + off);
        }
        __nv_bfloat16* dh = (mat ? sVh : sKh) + kj * 40 + cell * 8;
        __nv_bfloat16* dl = (mat ? sVl : sKl) + kj * 40 + cell * 8;
        *(uint4*)dh = vh;
        *(uint4*)dl = vl;
    }
    for (int t = tid; t < 27 * 32; t += 256) {
        rhs[(t >> 5) * RSTRIDE + (t & 31)] = rel_h[t];
        rws[(t >> 5) * RSTRIDE + (t & 31)] = rel_w[t];
    }
    __syncthreads();

    // ---- per-query bias tables (conflict-free rel reads now) ----
    for (int t = tid; t < 64 * WINS; t += 256) {
        const int q = t / WINS, j = t % WINS;
        const int y = q & 7, x = q >> 3;
        const float* rw = &rws[(j - y + WINS - 1) * RSTRIDE];
        const float* rh = &rhs[(j - x + WINS - 1) * RSTRIDE];
        float sw = 0.f, sh = 0.f;
        #pragma unroll
        for (int d = 0; d < 32; d++) {
            const float qv = __bfloat162float(sQh[q * 40 + d]) + __bfloat162float(sQl[q * 40 + d]);
            sw += qv * rw[d];
            sh += qv * rh[d];
        }
        bwv[t] = sw;
        bhv[t] = sh;
    }
    __syncthreads();

    const int w = tid >> 5, lane = tid & 31;
    const int p = w >> 1, hf = w & 1;
    const int q0 = p * 16, kb0 = hf * 112;
    const int gid = lane >> 2, tg = lane & 3;
    const int i8 = lane & 7;

    const uint32_t uQh = smem_u32(sQh), uQl = smem_u32(sQl);
    const uint32_t uKh = smem_u32(sKh), uKl = smem_u32(sKl);
    const uint32_t uVh = smem_u32(sVh), uVl = smem_u32(sVl);

    // ---- score MMAs: sc[14 n-blocks][4] ----
    float sc[14][4];
    #pragma unroll
    for (int nb = 0; nb < 14; nb++)
        #pragma unroll
        for (int c = 0; c < 4; c++) sc[nb][c] = 0.f;

    const int a_row = q0 + (((lane >> 3) & 1) << 3) + i8;
    const int a_col = (lane >> 4) << 3;
    const int k_rowoff = ((lane >> 4) << 3) + i8;
    const int k_col = ((lane >> 3) & 1) << 3;

    #pragma unroll
    for (int ks = 0; ks < 2; ks++) {
        uint32_t ah[4], al[4];
        const uint32_t aoff = (a_row * 40 + ks * 16 + a_col) * 2;
        ldm_x4(ah[0], ah[1], ah[2], ah[3], uQh + aoff);
        ldm_x4(al[0], al[1], al[2], al[3], uQl + aoff);
        #pragma unroll
        for (int kb2 = 0; kb2 < 7; kb2++) {
            const uint32_t koff = ((kb0 + kb2 * 16 + k_rowoff) * 40 + ks * 16 + k_col) * 2;
            uint32_t bh0, bh1, bh2, bh3, bl0, bl1, bl2, bl3;
            ldm_x4(bh0, bh1, bh2, bh3, uKh + koff);
            ldm_x4(bl0, bl1, bl2, bl3, uKl + koff);
            mma_bf16(sc[2 * kb2], ah[0], ah[1], ah[2], ah[3], bh0, bh1);
            mma_bf16(sc[2 * kb2], ah[0], ah[1], ah[2], ah[3], bl0, bl1);
            mma_bf16(sc[2 * kb2], al[0], al[1], al[2], al[3], bh0, bh1);
            mma_bf16(sc[2 * kb2 + 1], ah[0], ah[1], ah[2], ah[3], bh2, bh3);
            mma_bf16(sc[2 * kb2 + 1], ah[0], ah[1], ah[2], ah[3], bl2, bl3);
            mma_bf16(sc[2 * kb2 + 1], al[0], al[1], al[2], al[3], bh2, bh3);
        }
    }

    // ---- scale + bias + mask, row max ----
    const int q_lo = q0 + gid, q_hi = q_lo + 8;
    float m0 = -1e30f, m1 = -1e30f;
    #pragma unroll
    for (int nb = 0; nb < 14; nb++) {
        #pragma unroll
        for (int c = 0; c < 2; c++) {
            const int k = kb0 + nb * 8 + tg * 2 + c;
            if (k < NKEY) {
                const int kd = (k * 74899) >> 20;
                const int km = k - kd * 14;
                sc[nb][c]     = sc[nb][c]     * SCALE + bwv[q_lo * 14 + km] + bhv[q_lo * 14 + kd];
                sc[nb][2 + c] = sc[nb][2 + c] * SCALE + bwv[q_hi * 14 + km] + bhv[q_hi * 14 + kd];
            } else {
                sc[nb][c] = -1e30f;
                sc[nb][2 + c] = -1e30f;
            }
            m0 = fmaxf(m0, sc[nb][c]);
            m1 = fmaxf(m1, sc[nb][2 + c]);
        }
    }
    m0 = fmaxf(m0, __shfl_xor_sync(0xffffffffu, m0, 1));
    m0 = fmaxf(m0, __shfl_xor_sync(0xffffffffu, m0, 2));
    m1 = fmaxf(m1, __shfl_xor_sync(0xffffffffu, m1, 1));
    m1 = fmaxf(m1, __shfl_xor_sync(0xffffffffu, m1, 2));
    if (tg == 0) {
        redm[(p * 2 + hf) * 16 + gid] = m0;
        redm[(p * 2 + hf) * 16 + gid + 8] = m1;
    }
    __syncthreads();
    m0 = fmaxf(redm[(p * 2) * 16 + gid], redm[(p * 2 + 1) * 16 + gid]);
    m1 = fmaxf(redm[(p * 2) * 16 + gid + 8], redm[(p * 2 + 1) * 16 + gid + 8]);

    float s0 = 0.f, s1 = 0.f;
    #pragma unroll
    for (int nb = 0; nb < 14; nb++) {
        #pragma unroll
        for (int c = 0; c < 2; c++) {
            sc[nb][c] = __expf(sc[nb][c] - m0);
            s0 += sc[nb][c];
            sc[nb][2 + c] = __expf(sc[nb][2 + c] - m1);
            s1 += sc[nb][2 + c];
        }
    }
    s0 += __shfl_xor_sync(0xffffffffu, s0, 1);
    s0 += __shfl_xor_sync(0xffffffffu, s0, 2);
    s1 += __shfl_xor_sync(0xffffffffu, s1, 1);
    s1 += __shfl_xor_sync(0xffffffffu, s1, 2);
    if (tg == 0) {
        reds[(p * 2 + hf) * 16 + gid] = s0;
        reds[(p * 2 + hf) * 16 + gid + 8] = s1;
    }
    __syncthreads();
    const float inv0 = 1.f / (reds[(p * 2) * 16 + gid] + reds[(p * 2 + 1) * 16 + gid]);
    const float inv1 = 1.f / (reds[(p * 2) * 16 + gid + 8] + reds[(p * 2 + 1) * 16 + gid + 8]);

    // ---- ctx = P @ V via trans-ldmatrix V, 3-term ----
    float acc[4][4];
    #pragma unroll
    for (int nd = 0; nd < 4; nd++)
        #pragma unroll
        for (int c = 0; c < 4; c++) acc[nd][c] = 0.f;

    const int v_rowoff = (((lane >> 3) & 1) << 3) + i8;
    const int v_col = (lane >> 4) << 3;

    #pragma unroll
    for (int kb = 0; kb < 7; kb++) {
        uint32_t pah[4], pal[4];
        split2(sc[2 * kb][0], sc[2 * kb][1], pah[0], pal[0]);
        split2(sc[2 * kb][2], sc[2 * kb][3], pah[1], pal[1]);
        split2(sc[2 * kb + 1][0], sc[2 * kb + 1][1], pah[2], pal[2]);
        split2(sc[2 * kb + 1][2], sc[2 * kb + 1][3], pah[3], pal[3]);

        const int vrow = kb0 + kb * 16 + v_rowoff;
        uint32_t vh[8], vl[8];
        ldm_x4t(vh[0], vh[1], vh[2], vh[3], uVh + (vrow * 40 + v_col) * 2);
        ldm_x4t(vh[4], vh[5], vh[6], vh[7], uVh + (vrow * 40 + 16 + v_col) * 2);
        ldm_x4t(vl[0], vl[1], vl[2], vl[3], uVl + (vrow * 40 + v_col) * 2);
        ldm_x4t(vl[4], vl[5], vl[6], vl[7], uVl + (vrow * 40 + 16 + v_col) * 2);

        #pragma unroll
        for (int nd = 0; nd < 4; nd++) {
            const uint32_t b0h = vh[(nd >> 1) * 4 + (nd & 1) * 2];
            const uint32_t b1h = vh[(nd >> 1) * 4 + (nd & 1) * 2 + 1];
            const uint32_t b0l = vl[(nd >> 1) * 4 + (nd & 1) * 2];
            const uint32_t b1l = vl[(nd >> 1) * 4 + (nd & 1) * 2 + 1];
            mma_bf16(acc[nd], pah[0], pah[1], pah[2], pah[3], b0h, b1h);
            mma_bf16(acc[nd], pah[0], pah[1], pah[2], pah[3], b0l, b1l);
            mma_bf16(acc[nd], pal[0], pal[1], pal[2], pal[3], b0h, b1h);
        }
    }

    // ---- combine halves, normalize, store bf16 hi/lo ctx ----
    if (hf == 0) {
        #pragma unroll
        for (int nd = 0; nd < 4; nd++) {
            *(float2*)&ctxb[(q0 + gid) * 32 + nd * 8 + tg * 2] = make_float2(acc[nd][0], acc[nd][1]);
            *(float2*)&ctxb[(q0 + gid + 8) * 32 + nd * 8 + tg * 2] = make_float2(acc[nd][2], acc[nd][3]);
        }
    }
    __syncthreads();
    if (hf == 1) {
        const size_t base = ((size_t)(b * NBLK + n) * NQ + q0 + gid) * CDIM + h * DHEAD;
        const size_t base8 = base + 8 * CDIM;
        #pragma unroll
        for (int nd = 0; nd < 4; nd++) {
            const int dcol = nd * 8 + tg * 2;
            const float2 o0 = *(const float2*)&ctxb[(q0 + gid) * 32 + dcol];
            const float2 o1 = *(const float2*)&ctxb[(q0 + gid + 8) * 32 + dcol];
            uint32_t hi, lo;
            split2((acc[nd][0] + o0.x) * inv0, (acc[nd][1] + o0.y) * inv0, hi, lo);
            *(uint32_t*)&g_ch[base + dcol] = hi;
            *(uint32_t*)&g_cl[base + dcol] = lo;
            split2((acc[nd][2] + o1.x) * inv1, (acc[nd][3] + o1.y) * inv1, hi, lo);
            *(uint32_t*)&g_ch[base8 + dcol] = hi;
            *(uint32_t*)&g_cl[base8 + dcol] = lo;
        }
    }
}

// ============================================================================
extern "C" void kernel_launch(void* const* d_in, const int* in_sizes, int n_in,
                              void* d_out, int out_size) {
    const float* x     = (const float*)d_in[0];
    const float* w_q   = (const float*)d_in[1];
    const float* w_kv  = (const float*)d_in[2];
    const float* fc_w  = (const float*)d_in[3];
    const float* fc_b  = (const float*)d_in[4];
    const float* rel_h = (const float*)d_in[5];
    const float* rel_w = (const float*)d_in[6];
    float* out = (float*)d_out;

    __nv_bfloat16 *xh, *xl, *qh, *ql, *kvh, *kvl, *ch, *cl, *wh, *wl;
    cudaGetSymbolAddress((void**)&xh, g_xh);
    cudaGetSymbolAddress((void**)&xl, g_xl);
    cudaGetSymbolAddress((void**)&qh, g_qh);
    cudaGetSymbolAddress((void**)&ql, g_ql);
    cudaGetSymbolAddress((void**)&kvh, g_kvh);
    cudaGetSymbolAddress((void**)&kvl, g_kvl);
    cudaGetSymbolAddress((void**)&ch, g_ch);
    cudaGetSymbolAddress((void**)&cl, g_cl);
    cudaGetSymbolAddress((void**)&wh, g_wh);
    cudaGetSymbolAddress((void**)&wl, g_wl);

    cudaFuncSetAttribute(halo_attn, cudaFuncAttributeMaxDynamicSharedMemorySize, ATT_SMEM);

    split_w<<<1024, 256>>>(w_q, w_kv, fc_w);
    transpose_x<<<dim3(NPIX / 32, CDIM / 32, BATCH), dim3(32, 8)>>>(x);
    gemm_mma<<<dim3(MTOT / 128, 2), 256>>>(xh, xl, wh, wl, qh, ql, CDIM, 0, nullptr, nullptr);
    gemm_mma<<<dim3(MTOT / 128, 4), 256>>>(xh, xl, wh + 256 * CDIM, wl + 256 * CDIM,
                                           kvh, kvl, 2 * CDIM, 0, nullptr, nullptr);
    halo_attn<<<BATCH * NBLK * HEADS, 256, ATT_SMEM>>>(rel_h, rel_w);
    gemm_mma<<<dim3(MTOT / 128, 2), 256>>>(ch, cl, wh + 768 * CDIM, wl + 768 * CDIM,
                                           nullptr, nullptr, 0, 1, fc_b, out);
}

// round 12
// speedup vs baseline: 1.6036x; 1.0296x over previous
#include <cuda_runtime.h>
#include <cuda_bf16.h>
#include <cstdint>

#define BATCH 4
#define CDIM 256
#define HH 128
#define WW 128
#define NPIX (HH*WW)
#define HEADS 8
#define DHEAD 32
#define HALO 3
#define WINS 14
#define NBLK 256
#define NQ 64
#define NKEY 196
#define MTOT (BATCH*NPIX)
#define SCALE 0.17677669529663687f

// ---- scratch: bf16 hi/lo pairs ----
__device__ __nv_bfloat16 g_xh [(size_t)MTOT * CDIM];
__device__ __nv_bfloat16 g_xl [(size_t)MTOT * CDIM];
__device__ __nv_bfloat16 g_qh [(size_t)MTOT * CDIM];
__device__ __nv_bfloat16 g_ql [(size_t)MTOT * CDIM];
__device__ __nv_bfloat16 g_kvh[(size_t)MTOT * 2 * CDIM];
__device__ __nv_bfloat16 g_kvl[(size_t)MTOT * 2 * CDIM];
__device__ __nv_bfloat16 g_ch [(size_t)MTOT * CDIM];
__device__ __nv_bfloat16 g_cl [(size_t)MTOT * CDIM];
__device__ __nv_bfloat16 g_wh [(size_t)1024 * CDIM];
__device__ __nv_bfloat16 g_wl [(size_t)1024 * CDIM];

// ---------------- helpers ----------------
__device__ __forceinline__ uint32_t smem_u32(const void* p) {
    uint32_t a;
    asm("{ .reg .u64 t; cvta.to.shared.u64 t, %1; cvt.u32.u64 %0, t; }" : "=r"(a) : "l"(p));
    return a;
}
__device__ __forceinline__ void ldm_x4(uint32_t& r0, uint32_t& r1, uint32_t& r2, uint32_t& r3,
                                       uint32_t addr) {
    asm volatile("ldmatrix.sync.aligned.m8n8.x4.shared.b16 {%0,%1,%2,%3}, [%4];"
                 : "=r"(r0), "=r"(r1), "=r"(r2), "=r"(r3) : "r"(addr));
}
__device__ __forceinline__ void ldm_x4t(uint32_t& r0, uint32_t& r1, uint32_t& r2, uint32_t& r3,
                                        uint32_t addr) {
    asm volatile("ldmatrix.sync.aligned.m8n8.x4.trans.shared.b16 {%0,%1,%2,%3}, [%4];"
                 : "=r"(r0), "=r"(r1), "=r"(r2), "=r"(r3) : "r"(addr));
}
__device__ __forceinline__ void ldm_x2(uint32_t& r0, uint32_t& r1, uint32_t addr) {
    asm volatile("ldmatrix.sync.aligned.m8n8.x2.shared.b16 {%0,%1}, [%2];"
                 : "=r"(r0), "=r"(r1) : "r"(addr));
}
__device__ __forceinline__ void mma_bf16(float* d,
                                         uint32_t a0, uint32_t a1, uint32_t a2, uint32_t a3,
                                         uint32_t b0, uint32_t b1) {
    asm volatile("mma.sync.aligned.m16n8k16.row.col.f32.bf16.bf16.f32 "
                 "{%0,%1,%2,%3}, {%4,%5,%6,%7}, {%8,%9}, {%0,%1,%2,%3};"
                 : "+f"(d[0]), "+f"(d[1]), "+f"(d[2]), "+f"(d[3])
                 : "r"(a0), "r"(a1), "r"(a2), "r"(a3), "r"(b0), "r"(b1));
}
__device__ __forceinline__ void split2(float x, float y, uint32_t& hi, uint32_t& lo) {
    __nv_bfloat162 h2, l2;
    h2.x = __float2bfloat16_rn(x);
    h2.y = __float2bfloat16_rn(y);
    l2.x = __float2bfloat16_rn(x - __bfloat162float(h2.x));
    l2.y = __float2bfloat16_rn(y - __bfloat162float(h2.y));
    hi = *(uint32_t*)&h2;
    lo = *(uint32_t*)&l2;
}

// ============================================================================
// x[b][c][p] -> x_t[(b,p)][c] split to bf16 hi/lo
// ============================================================================
__global__ __launch_bounds__(256) void transpose_x(const float* __restrict__ x) {
    __shared__ float t[32][33];
    const int b = blockIdx.z, c0 = blockIdx.y * 32, p0 = blockIdx.x * 32;
    const int tx = threadIdx.x, ty = threadIdx.y;
    const float* src = x + (size_t)b * CDIM * NPIX;
    #pragma unroll
    for (int i = ty; i < 32; i += 8)
        t[i][tx] = src[(size_t)(c0 + i) * NPIX + p0 + tx];
    __syncthreads();
    #pragma unroll
    for (int i = ty; i < 32; i += 8) {
        const float v = t[tx][i];
        const size_t o = ((size_t)b * NPIX + p0 + i) * CDIM + c0 + tx;
        const __nv_bfloat16 h = __float2bfloat16_rn(v);
        g_xh[o] = h;
        g_xl[o] = __float2bfloat16_rn(v - __bfloat162float(h));
    }
}

__global__ __launch_bounds__(256) void split_w(const float* __restrict__ wq,
                                               const float* __restrict__ wkv,
                                               const float* __restrict__ fcw) {
    const int idx = blockIdx.x * 256 + threadIdx.x;
    const int r = idx >> 8, c = idx & 255;
    float v;
    if (r < 256) v = wq[r * 256 + c];
    else if (r < 768) v = wkv[(r - 256) * 256 + c];
    else v = fcw[(r - 768) * 256 + c];
    const __nv_bfloat16 h = __float2bfloat16_rn(v);
    g_wh[idx] = h;
    g_wl[idx] = __float2bfloat16_rn(v - __bfloat162float(h));
}

// ============================================================================
// TN GEMM via mma.sync bf16 3-term (R6 proven: static smem, 2 CTAs/SM).
// mode 0: write bf16 hi/lo to Ch/Cl. mode 1: fp32 +bias, scatter to BCHW out.
// ============================================================================
#define LROW 40

__global__ __launch_bounds__(256) void gemm_mma(const __nv_bfloat16* __restrict__ Ah,
                                                const __nv_bfloat16* __restrict__ Al,
                                                const __nv_bfloat16* __restrict__ Bh,
                                                const __nv_bfloat16* __restrict__ Bl,
                                                __nv_bfloat16* __restrict__ Ch,
                                                __nv_bfloat16* __restrict__ Cl,
                                                int ldc, int mode,
                                                const float* __restrict__ fcb,
                                                float* __restrict__ out) {
    __shared__ __align__(16) __nv_bfloat16 sAh[128 * LROW];
    __shared__ __align__(16) __nv_bfloat16 sAl[128 * LROW];
    __shared__ __align__(16) __nv_bfloat16 sBh[128 * LROW];
    __shared__ __align__(16) __nv_bfloat16 sBl[128 * LROW];

    const int tid = threadIdx.x, wid = tid >> 5, lane = tid & 31;
    const int wm = wid >> 2, wn = wid & 3;
    const size_t m0 = (size_t)blockIdx.x * 128;
    const size_t n0 = (size_t)blockIdx.y * 128;

    const uint32_t uAh = smem_u32(sAh), uAl = smem_u32(sAl);
    const uint32_t uBh = smem_u32(sBh), uBl = smem_u32(sBl);

    float acc[4][4][4];
    #pragma unroll
    for (int a = 0; a < 4; a++)
        #pragma unroll
        for (int b = 0; b < 4; b++)
            #pragma unroll
            for (int c = 0; c < 4; c++) acc[a][b][c] = 0.f;

    const int i8 = lane & 7, g = lane >> 3;
    const int a_r = wm * 64 + ((g & 1) << 3) + i8;
    const int a_c = (g >> 1) << 3;
    const int b_r = wn * 32 + i8;
    const int b_sel = (lane >> 3) & 1;

    for (int it = 0; it < 8; it++) {
        if (it) __syncthreads();
        #pragma unroll
        for (int r = 0; r < 4; r++) {
            const int id = tid + 256 * r;
            const int mat = id >> 9;
            const int row = (id >> 2) & 127;
            const int cell = id & 3;
            const size_t off = ((mat ? n0 : m0) + row) * CDIM + it * 32 + cell * 8;
            const uint4 vh = *(const uint4*)((mat ? Bh : Ah) + off);
            const uint4 vl = *(const uint4*)((mat ? Bl : Al) + off);
            __nv_bfloat16* dh = (mat ? sBh : sAh) + row * LROW + cell * 8;
            __nv_bfloat16* dl = (mat ? sBl : sAl) + row * LROW + cell * 8;
            *(uint4*)dh = vh;
            *(uint4*)dl = vl;
        }
        __syncthreads();

        #pragma unroll
        for (int ks = 0; ks < 2; ks++) {
            const int kb = ks * 16;
            uint32_t ah[4][4], al[4][4];
            #pragma unroll
            for (int ms = 0; ms < 4; ms++) {
                const uint32_t off = ((a_r + ms * 16) * LROW + kb + a_c) * 2;
                ldm_x4(ah[ms][0], ah[ms][1], ah[ms][2], ah[ms][3], uAh + off);
                ldm_x4(al[ms][0], al[ms][1], al[ms][2], al[ms][3], uAl + off);
            }
            #pragma unroll
            for (int ns = 0; ns < 4; ns++) {
                const uint32_t boff = ((b_r + ns * 8) * LROW + kb + b_sel * 8) * 2;
                uint32_t bh0, bh1, bl0, bl1;
                ldm_x2(bh0, bh1, uBh + boff);
                ldm_x2(bl0, bl1, uBl + boff);
                #pragma unroll
                for (int ms = 0; ms < 4; ms++) {
                    mma_bf16(acc[ms][ns], ah[ms][0], ah[ms][1], ah[ms][2], ah[ms][3], bh0, bh1);
                    mma_bf16(acc[ms][ns], ah[ms][0], ah[ms][1], ah[ms][2], ah[ms][3], bl0, bl1);
                    mma_bf16(acc[ms][ns], al[ms][0], al[ms][1], al[ms][2], al[ms][3], bh0, bh1);
                }
            }
        }
    }

    const int er = lane >> 2, ec = (lane & 3) * 2;
    #pragma unroll
    for (int ms = 0; ms < 4; ms++) {
        #pragma unroll
        for (int ns = 0; ns < 4; ns++) {
            const float* d = acc[ms][ns];
            const size_t m = m0 + wm * 64 + ms * 16 + er;
            const int nl = (int)n0 + wn * 32 + ns * 8 + ec;
            if (mode == 0) {
                #pragma unroll
                for (int rr = 0; rr < 2; rr++) {
                    uint32_t hi, lo;
                    split2(d[rr * 2], d[rr * 2 + 1], hi, lo);
                    *(uint32_t*)&Ch[(m + rr * 8) * ldc + nl] = hi;
                    *(uint32_t*)&Cl[(m + rr * 8) * ldc + nl] = lo;
                }
            } else {
                #pragma unroll
                for (int rr = 0; rr < 2; rr++) {
                    const size_t mm = m + rr * 8;
                    const int b = (int)(mm >> 14), n = (int)((mm >> 6) & 255), q = (int)(mm & 63);
                    const int orow = ((n >> 4) << 3) + (q >> 3);
                    const int ocol = ((n & 15) << 3) + (q & 7);
                    const size_t base = (((size_t)b * CDIM) << 14) + (orow << 7) + ocol;
                    out[base + ((size_t)nl << 14)]       = d[rr * 2]     + fcb[nl];
                    out[base + ((size_t)(nl + 1) << 14)] = d[rr * 2 + 1] + fcb[nl + 1];
                }
            }
        }
    }
}

// ============================================================================
// MMA halo attention. R10 structure, but bias tables computed via MMA:
// bias_w_all[q][t] = Q[q]·rel_w[t], bias_h_all[q][t] = Q[q]·rel_h[t]
// stored as float [64][27]; rel staging tiles live in smem aliased ONLY over
// later-phase buffers (redm/reds/ctxb). Stores predicated col<27 so garbage
// in uninitialized staging rows 27-31 never reaches a read value.
// ============================================================================
#define BSTRIDE 27
#define ATT_SMEM 105984

__global__ __launch_bounds__(256, 2) void halo_attn(const float* __restrict__ rel_h,
                                                    const float* __restrict__ rel_w) {
    extern __shared__ __align__(16) char smx[];
    __nv_bfloat16* sQh = (__nv_bfloat16*)(smx);            // [64][40]
    __nv_bfloat16* sQl = (__nv_bfloat16*)(smx + 5120);
    __nv_bfloat16* sKh = (__nv_bfloat16*)(smx + 10240);    // [224][40]
    __nv_bfloat16* sKl = (__nv_bfloat16*)(smx + 28160);
    __nv_bfloat16* sVh = (__nv_bfloat16*)(smx + 46080);    // [224][40] key-major
    __nv_bfloat16* sVl = (__nv_bfloat16*)(smx + 64000);
    float* bAw  = (float*)(smx + 81920);                   // [64][27]
    float* bAh  = (float*)(smx + 88832);                   // [64][27]
    float* redm = (float*)(smx + 95744);                   // [4][2][16]
    float* reds = (float*)(smx + 96256);
    float* ctxb = (float*)(smx + 96768);                   // [64][32] -> 104960
    // staging (bias phase only; aliases redm/reds/ctxb which are later-phase)
    __nv_bfloat16* sRWh = (__nv_bfloat16*)(smx + 95744);   // [32][40]
    __nv_bfloat16* sRWl = (__nv_bfloat16*)(smx + 98304);
    __nv_bfloat16* sRHh = (__nv_bfloat16*)(smx + 100864);
    __nv_bfloat16* sRHl = (__nv_bfloat16*)(smx + 103424);  // ends 105984

    const int bid = blockIdx.x;
    const int h = bid & 7;
    const int n = (bid >> 3) & 255;
    const int b = bid >> 11;
    const int r0 = (n >> 4) << 3;
    const int c0 = (n & 15) << 3;
    const int tid = threadIdx.x;

    // ---- load Q ----
    {
        const int row = tid >> 2, cell = tid & 3;
        const int pix = (r0 + (row >> 3)) * WW + c0 + (row & 7);
        const size_t gr = ((size_t)b * NPIX + pix) * CDIM + h * DHEAD + cell * 8;
        *(uint4*)(sQh + row * 40 + cell * 8) = *(const uint4*)(g_qh + gr);
        *(uint4*)(sQl + row * 40 + cell * 8) = *(const uint4*)(g_ql + gr);
    }
    // ---- load K/V windows, zero pads ----
    for (int t = tid; t < 1792; t += 256) {
        const int kj = t >> 3, rem = t & 7;
        const int mat = rem >> 2, cell = rem & 3;
        const int rr = r0 - HALO + kj / WINS;
        const int cc = c0 - HALO + kj % WINS;
        uint4 vh = make_uint4(0, 0, 0, 0), vl = vh;
        if (kj < NKEY && rr >= 0 && rr < HH && cc >= 0 && cc < WW) {
            const size_t off = ((size_t)b * NPIX + rr * WW + cc) * (2 * CDIM)
                             + (mat ? CDIM : 0) + h * DHEAD + cell * 8;
            vh = *(const uint4*)(g_kvh + off);
            vl = *(const uint4*)(g_kvl + off);
        }
        __nv_bfloat16* dh = (mat ? sVh : sKh) + kj * 40 + cell * 8;
        __nv_bfloat16* dl = (mat ? sVl : sKl) + kj * 40 + cell * 8;
        *(uint4*)dh = vh;
        *(uint4*)dl = vl;
    }
    // ---- stage rel tables as bf16 hi/lo, rows 0..26 (27..31 don't matter) ----
    for (int t = tid; t < 1728; t += 256) {
        const int tbl = t / 864;
        const int e = t - tbl * 864;
        const int row = e >> 5, d = e & 31;
        const float v = tbl ? rel_h[e] : rel_w[e];
        const __nv_bfloat16 hh = __float2bfloat16_rn(v);
        const __nv_bfloat16 ll = __float2bfloat16_rn(v - __bfloat162float(hh));
        __nv_bfloat16* ph = tbl ? sRHh : sRWh;
        __nv_bfloat16* pl = tbl ? sRHl : sRWl;
        ph[row * 40 + d] = hh;
        pl[row * 40 + d] = ll;
    }
    __syncthreads();

    const int w = tid >> 5, lane = tid & 31;
    const int gid = lane >> 2, tg = lane & 3;
    const int i8 = lane & 7;
    const int arow_g = (((lane >> 3) & 1) << 3) + i8;
    const int acol = (lane >> 4) << 3;
    const int krow = ((lane >> 4) << 3) + i8;
    const int kcol = ((lane >> 3) & 1) << 3;

    const uint32_t uQh = smem_u32(sQh), uQl = smem_u32(sQl);
    const uint32_t uKh = smem_u32(sKh), uKl = smem_u32(sKl);
    const uint32_t uVh = smem_u32(sVh), uVl = smem_u32(sVl);

    // ---- bias tables via MMA: warps 0-3 -> bAw, warps 4-7 -> bAh ----
    {
        const int rq = (w & 3) * 16;
        const bool isH = (w >= 4);
        uint32_t qah[2][4], qal[2][4];
        #pragma unroll
        for (int ks = 0; ks < 2; ks++) {
            const uint32_t off = ((rq + arow_g) * 40 + ks * 16 + acol) * 2;
            ldm_x4(qah[ks][0], qah[ks][1], qah[ks][2], qah[ks][3], uQh + off);
            ldm_x4(qal[ks][0], qal[ks][1], qal[ks][2], qal[ks][3], uQl + off);
        }
        const uint32_t uTh = smem_u32(isH ? sRHh : sRWh);
        const uint32_t uTl = smem_u32(isH ? sRHl : sRWl);
        float ob[4][4];
        #pragma unroll
        for (int a = 0; a < 4; a++)
            #pragma unroll
            for (int c = 0; c < 4; c++) ob[a][c] = 0.f;
        #pragma unroll
        for (int ks = 0; ks < 2; ks++) {
            #pragma unroll
            for (int t2 = 0; t2 < 2; t2++) {
                const uint32_t toff = ((t2 * 16 + krow) * 40 + ks * 16 + kcol) * 2;
                uint32_t bh0, bh1, bh2, bh3, bl0, bl1, bl2, bl3;
                ldm_x4(bh0, bh1, bh2, bh3, uTh + toff);
                ldm_x4(bl0, bl1, bl2, bl3, uTl + toff);
                mma_bf16(ob[t2 * 2], qah[ks][0], qah[ks][1], qah[ks][2], qah[ks][3], bh0, bh1);
                mma_bf16(ob[t2 * 2], qah[ks][0], qah[ks][1], qah[ks][2], qah[ks][3], bl0, bl1);
                mma_bf16(ob[t2 * 2], qal[ks][0], qal[ks][1], qal[ks][2], qal[ks][3], bh0, bh1);
                mma_bf16(ob[t2 * 2 + 1], qah[ks][0], qah[ks][1], qah[ks][2], qah[ks][3], bh2, bh3);
                mma_bf16(ob[t2 * 2 + 1], qah[ks][0], qah[ks][1], qah[ks][2], qah[ks][3], bl2, bl3);
                mma_bf16(ob[t2 * 2 + 1], qal[ks][0], qal[ks][1], qal[ks][2], qal[ks][3], bh2, bh3);
            }
        }
        // store (dedicated region, no overlap with staging) — predicated col<27
        float* dst = isH ? bAh : bAw;
        #pragma unroll
        for (int nbO = 0; nbO < 4; nbO++) {
            const int col0 = nbO * 8 + tg * 2;
            if (col0 < BSTRIDE) {
                dst[(rq + gid) * BSTRIDE + col0] = ob[nbO][0];
                dst[(rq + gid + 8) * BSTRIDE + col0] = ob[nbO][2];
            }
            if (col0 + 1 < BSTRIDE) {
                dst[(rq + gid) * BSTRIDE + col0 + 1] = ob[nbO][1];
                dst[(rq + gid + 8) * BSTRIDE + col0 + 1] = ob[nbO][3];
            }
        }
    }
    __syncthreads();   // bias tables complete; staging dead from here on

    const int p = w >> 1, hf = w & 1;
    const int q0 = p * 16, kb0 = hf * 112;

    // ---- score MMAs: sc[14 n-blocks][4] ----
    float sc[14][4];
    #pragma unroll
    for (int nb = 0; nb < 14; nb++)
        #pragma unroll
        for (int c = 0; c < 4; c++) sc[nb][c] = 0.f;

    const int a_row = q0 + arow_g;

    #pragma unroll
    for (int ks = 0; ks < 2; ks++) {
        uint32_t ah[4], al[4];
        const uint32_t aoff = (a_row * 40 + ks * 16 + acol) * 2;
        ldm_x4(ah[0], ah[1], ah[2], ah[3], uQh + aoff);
        ldm_x4(al[0], al[1], al[2], al[3], uQl + aoff);
        #pragma unroll
        for (int kb2 = 0; kb2 < 7; kb2++) {
            const uint32_t koff = ((kb0 + kb2 * 16 + krow) * 40 + ks * 16 + kcol) * 2;
            uint32_t bh0, bh1, bh2, bh3, bl0, bl1, bl2, bl3;
            ldm_x4(bh0, bh1, bh2, bh3, uKh + koff);
            ldm_x4(bl0, bl1, bl2, bl3, uKl + koff);
            mma_bf16(sc[2 * kb2], ah[0], ah[1], ah[2], ah[3], bh0, bh1);
            mma_bf16(sc[2 * kb2], ah[0], ah[1], ah[2], ah[3], bl0, bl1);
            mma_bf16(sc[2 * kb2], al[0], al[1], al[2], al[3], bh0, bh1);
            mma_bf16(sc[2 * kb2 + 1], ah[0], ah[1], ah[2], ah[3], bh2, bh3);
            mma_bf16(sc[2 * kb2 + 1], ah[0], ah[1], ah[2], ah[3], bl2, bl3);
            mma_bf16(sc[2 * kb2 + 1], al[0], al[1], al[2], al[3], bh2, bh3);
        }
    }

    // ---- scale + bias + mask, row max ----
    const int q_lo = q0 + gid, q_hi = q_lo + 8;
    const int x_lo = q_lo >> 3, x_hi = q_hi >> 3;
    float m0 = -1e30f, m1 = -1e30f;
    #pragma unroll
    for (int nb = 0; nb < 14; nb++) {
        #pragma unroll
        for (int c = 0; c < 2; c++) {
            const int k = kb0 + nb * 8 + tg * 2 + c;
            if (k < NKEY) {
                const int kd = (k * 74899) >> 20;
                const int km = k - kd * 14;
                const int jw = km - gid + 13;
                sc[nb][c]     = sc[nb][c]     * SCALE + bAw[q_lo * BSTRIDE + jw]
                              + bAh[q_lo * BSTRIDE + kd - x_lo + 13];
                sc[nb][2 + c] = sc[nb][2 + c] * SCALE + bAw[q_hi * BSTRIDE + jw]
                              + bAh[q_hi * BSTRIDE + kd - x_hi + 13];
            } else {
                sc[nb][c] = -1e30f;
                sc[nb][2 + c] = -1e30f;
            }
            m0 = fmaxf(m0, sc[nb][c]);
            m1 = fmaxf(m1, sc[nb][2 + c]);
        }
    }
    m0 = fmaxf(m0, __shfl_xor_sync(0xffffffffu, m0, 1));
    m0 = fmaxf(m0, __shfl_xor_sync(0xffffffffu, m0, 2));
    m1 = fmaxf(m1, __shfl_xor_sync(0xffffffffu, m1, 1));
    m1 = fmaxf(m1, __shfl_xor_sync(0xffffffffu, m1, 2));
    if (tg == 0) {
        redm[(p * 2 + hf) * 16 + gid] = m0;
        redm[(p * 2 + hf) * 16 + gid + 8] = m1;
    }
    __syncthreads();
    m0 = fmaxf(redm[(p * 2) * 16 + gid], redm[(p * 2 + 1) * 16 + gid]);
    m1 = fmaxf(redm[(p * 2) * 16 + gid + 8], redm[(p * 2 + 1) * 16 + gid + 8]);

    float s0 = 0.f, s1 = 0.f;
    #pragma unroll
    for (int nb = 0; nb < 14; nb++) {
        #pragma unroll
        for (int c = 0; c < 2; c++) {
            sc[nb][c] = __expf(sc[nb][c] - m0);
            s0 += sc[nb][c];
            sc[nb][2 + c] = __expf(sc[nb][2 + c] - m1);
            s1 += sc[nb][2 + c];
        }
    }
    s0 += __shfl_xor_sync(0xffffffffu, s0, 1);
    s0 += __shfl_xor_sync(0xffffffffu, s0, 2);
    s1 += __shfl_xor_sync(0xffffffffu, s1, 1);
    s1 += __shfl_xor_sync(0xffffffffu, s1, 2);
    if (tg == 0) {
        reds[(p * 2 + hf) * 16 + gid] = s0;
        reds[(p * 2 + hf) * 16 + gid + 8] = s1;
    }
    __syncthreads();
    const float inv0 = 1.f / (reds[(p * 2) * 16 + gid] + reds[(p * 2 + 1) * 16 + gid]);
    const float inv1 = 1.f / (reds[(p * 2) * 16 + gid + 8] + reds[(p * 2 + 1) * 16 + gid + 8]);

    // ---- ctx = P @ V via trans-ldmatrix V, 3-term ----
    float acc[4][4];
    #pragma unroll
    for (int nd = 0; nd < 4; nd++)
        #pragma unroll
        for (int c = 0; c < 4; c++) acc[nd][c] = 0.f;

    const int v_rowoff = arow_g;
    const int v_col = (lane >> 4) << 3;

    #pragma unroll
    for (int kb = 0; kb < 7; kb++) {
        uint32_t pah[4], pal[4];
        split2(sc[2 * kb][0], sc[2 * kb][1], pah[0], pal[0]);
        split2(sc[2 * kb][2], sc[2 * kb][3], pah[1], pal[1]);
        split2(sc[2 * kb + 1][0], sc[2 * kb + 1][1], pah[2], pal[2]);
        split2(sc[2 * kb + 1][2], sc[2 * kb + 1][3], pah[3], pal[3]);

        const int vrow = kb0 + kb * 16 + v_rowoff;
        uint32_t vh[8], vl[8];
        ldm_x4t(vh[0], vh[1], vh[2], vh[3], uVh + (vrow * 40 + v_col) * 2);
        ldm_x4t(vh[4], vh[5], vh[6], vh[7], uVh + (vrow * 40 + 16 + v_col) * 2);
        ldm_x4t(vl[0], vl[1], vl[2], vl[3], uVl + (vrow * 40 + v_col) * 2);
        ldm_x4t(vl[4], vl[5], vl[6], vl[7], uVl + (vrow * 40 + 16 + v_col) * 2);

        #pragma unroll
        for (int nd = 0; nd < 4; nd++) {
            const uint32_t b0h = vh[(nd >> 1) * 4 + (nd & 1) * 2];
            const uint32_t b1h = vh[(nd >> 1) * 4 + (nd & 1) * 2 + 1];
            const uint32_t b0l = vl[(nd >> 1) * 4 + (nd & 1) * 2];
            const uint32_t b1l = vl[(nd >> 1) * 4 + (nd & 1) * 2 + 1];
            mma_bf16(acc[nd], pah[0], pah[1], pah[2], pah[3], b0h, b1h);
            mma_bf16(acc[nd], pah[0], pah[1], pah[2], pah[3], b0l, b1l);
            mma_bf16(acc[nd], pal[0], pal[1], pal[2], pal[3], b0h, b1h);
        }
    }

    // ---- combine halves, normalize, store bf16 hi/lo ctx ----
    if (hf == 0) {
        #pragma unroll
        for (int nd = 0; nd < 4; nd++) {
            *(float2*)&ctxb[(q0 + gid) * 32 + nd * 8 + tg * 2] = make_float2(acc[nd][0], acc[nd][1]);
            *(float2*)&ctxb[(q0 + gid + 8) * 32 + nd * 8 + tg * 2] = make_float2(acc[nd][2], acc[nd][3]);
        }
    }
    __syncthreads();
    if (hf == 1) {
        const size_t base = ((size_t)(b * NBLK + n) * NQ + q0 + gid) * CDIM + h * DHEAD;
        const size_t base8 = base + 8 * CDIM;
        #pragma unroll
        for (int nd = 0; nd < 4; nd++) {
            const int dcol = nd * 8 + tg * 2;
            const float2 o0 = *(const float2*)&ctxb[(q0 + gid) * 32 + dcol];
            const float2 o1 = *(const float2*)&ctxb[(q0 + gid + 8) * 32 + dcol];
            uint32_t hi, lo;
            split2((acc[nd][0] + o0.x) * inv0, (acc[nd][1] + o0.y) * inv0, hi, lo);
            *(uint32_t*)&g_ch[base + dcol] = hi;
            *(uint32_t*)&g_cl[base + dcol] = lo;
            split2((acc[nd][2] + o1.x) * inv1, (acc[nd][3] + o1.y) * inv1, hi, lo);
            *(uint32_t*)&g_ch[base8 + dcol] = hi;
            *(uint32_t*)&g_cl[base8 + dcol] = lo;
        }
    }
}

// ============================================================================
extern "C" void kernel_launch(void* const* d_in, const int* in_sizes, int n_in,
                              void* d_out, int out_size) {
    const float* x     = (const float*)d_in[0];
    const float* w_q   = (const float*)d_in[1];
    const float* w_kv  = (const float*)d_in[2];
    const float* fc_w  = (const float*)d_in[3];
    const float* fc_b  = (const float*)d_in[4];
    const float* rel_h = (const float*)d_in[5];
    const float* rel_w = (const float*)d_in[6];
    float* out = (float*)d_out;

    __nv_bfloat16 *xh, *xl, *qh, *ql, *kvh, *kvl, *ch, *cl, *wh, *wl;
    cudaGetSymbolAddress((void**)&xh, g_xh);
    cudaGetSymbolAddress((void**)&xl, g_xl);
    cudaGetSymbolAddress((void**)&qh, g_qh);
    cudaGetSymbolAddress((void**)&ql, g_ql);
    cudaGetSymbolAddress((void**)&kvh, g_kvh);
    cudaGetSymbolAddress((void**)&kvl, g_kvl);
    cudaGetSymbolAddress((void**)&ch, g_ch);
    cudaGetSymbolAddress((void**)&cl, g_cl);
    cudaGetSymbolAddress((void**)&wh, g_wh);
    cudaGetSymbolAddress((void**)&wl, g_wl);

    cudaFuncSetAttribute(halo_attn, cudaFuncAttributeMaxDynamicSharedMemorySize, ATT_SMEM);

    split_w<<<1024, 256>>>(w_q, w_kv, fc_w);
    transpose_x<<<dim3(NPIX / 32, CDIM / 32, BATCH), dim3(32, 8)>>>(x);
    gemm_mma<<<dim3(MTOT / 128, 2), 256>>>(xh, xl, wh, wl, qh, ql, CDIM, 0, nullptr, nullptr);
    gemm_mma<<<dim3(MTOT / 128, 4), 256>>>(xh, xl, wh + 256 * CDIM, wl + 256 * CDIM,
                                           kvh, kvl, 2 * CDIM, 0, nullptr, nullptr);
    halo_attn<<<BATCH * NBLK * HEADS, 256, ATT_SMEM>>>(rel_h, rel_w);
    gemm_mma<<<dim3(MTOT / 128, 2), 256>>>(ch, cl, wh + 768 * CDIM, wl + 768 * CDIM,
                                           nullptr, nullptr, 0, 1, fc_b, out);
}